// round 15
// baseline (speedup 1.0000x reference)
#include <cuda_runtime.h>
#include <cstdint>

// Effective matrix, tf32, mma-fragment order, nf-pairwise 16B-packed:
// d_Bf[kchunk][kstep][npair][lane][half][idx], 4*4*8*32*2*2 = 16384 floats
__device__ float d_Bf[16384];

// ---- constants (match reference float32 values) ----
#define C0_     0.02795084971874737f   // sqrt(1/1280)
#define C1_     0.05103103630798288f   // sqrt(3/1152)
#define C2_     0.09882117688026186f   // sqrt(5/512)
#define INV_S3_ 0.57735026918962576f
#define INV_S5_ 0.44721359549995794f
#define RS0_    0.17677669529663687f   // 1/sqrt(32)
#define RS1_    0.25f                  // 1/sqrt(16)
#define RS2_    0.35355339059327373f   // 1/sqrt(8)

__device__ __forceinline__ void make_w3j(float C[3][3][5]) {
    const float s2 = 0.7071067811865476f;
    const float s6 = 0.4082482904638630f;
    const float i5 = 0.4472135954999579f;
#pragma unroll
    for (int i = 0; i < 3; i++)
#pragma unroll
        for (int j = 0; j < 3; j++)
#pragma unroll
            for (int k = 0; k < 5; k++) C[i][j][k] = 0.f;
    C[0][2][0] = s2;  C[2][0][0] = s2;
    C[0][1][1] = s2;  C[1][0][1] = s2;
    C[1][1][2] = 2.0f * s6;
    C[0][0][2] = -s6; C[2][2][2] = -s6;
    C[1][2][3] = s2;  C[2][1][3] = s2;
    C[2][2][4] = s2;  C[0][0][4] = -s2;
#pragma unroll
    for (int i = 0; i < 3; i++)
#pragma unroll
        for (int j = 0; j < 3; j++)
#pragma unroll
            for (int k = 0; k < 5; k++) C[i][j][k] *= i5;
}

__device__ __forceinline__ uint32_t f2tf32(float v) {
    uint32_t t;
    asm("cvt.rna.tf32.f32 %0, %1;" : "=r"(t) : "f"(v));
    return t;
}

// One thread per (o, g) entry of the effective 120x120 map (padded 128x128).
__global__ void build_M(const float* __restrict__ field,
                        const float* __restrict__ w000,
                        const float* __restrict__ w011,
                        const float* __restrict__ w101,
                        const float* __restrict__ w110,
                        const float* __restrict__ w112,
                        const float* __restrict__ w202,
                        const float* __restrict__ w211,
                        const float* __restrict__ wl0,
                        const float* __restrict__ wl1,
                        const float* __restrict__ wl2)
{
    const int o = blockIdx.x;
    const int g = threadIdx.x;
    const float* f0 = field;
    const float* f1 = field + 32;

    float val = 0.f;
    if (o < 120 && g < 120) {
        float W[3][3][5];
        make_w3j(W);
        if (o < 32) {
            const int w = o;
            if (g < 32) {
                const int u = g;
                float s = 0.f;
#pragma unroll
                for (int v = 0; v < 32; v++) s += w000[u * 1024 + v * 32 + w] * f0[v];
                val = C0_ * s + wl0[u * 32 + w] * RS0_;
            } else if (g < 80) {
                const int u = (g - 32) / 3, i = (g - 32) % 3;
                float s = 0.f;
#pragma unroll
                for (int v = 0; v < 16; v++) s += w110[u * 512 + v * 32 + w] * f1[v * 3 + i];
                val = C0_ * INV_S3_ * s;
            }
        } else if (o < 80) {
            const int w = (o - 32) / 3, j = (o - 32) % 3;
            if (g < 32) {
                const int u = g;
                float s = 0.f;
#pragma unroll
                for (int v = 0; v < 16; v++) s += w011[u * 256 + v * 16 + w] * f1[v * 3 + j];
                val = C1_ * INV_S3_ * s;
            } else if (g < 80) {
                const int u = (g - 32) / 3, i = (g - 32) % 3;
                if (i == j) {
                    float s = 0.f;
#pragma unroll
                    for (int v = 0; v < 32; v++) s += w101[u * 512 + v * 16 + w] * f0[v];
                    val = C1_ * INV_S3_ * s + wl1[u * 16 + w] * RS1_;
                }
            } else {
                const int u = (g - 80) / 5, k = (g - 80) % 5;
                float s = 0.f;
#pragma unroll
                for (int i = 0; i < 3; i++) {
                    const float wj = W[i][j][k];
                    if (wj != 0.f) {
                        float t = 0.f;
#pragma unroll
                        for (int v = 0; v < 16; v++) t += w211[u * 256 + v * 16 + w] * f1[v * 3 + i];
                        s += wj * t;
                    }
                }
                val = C1_ * s;
            }
        } else {
            const int w = (o - 80) / 5, k = (o - 80) % 5;
            if (g >= 32 && g < 80) {
                const int u = (g - 32) / 3, i = (g - 32) % 3;
                float s = 0.f;
#pragma unroll
                for (int j = 0; j < 3; j++) {
                    const float wj = W[i][j][k];
                    if (wj != 0.f) {
                        float t = 0.f;
#pragma unroll
                        for (int v = 0; v < 16; v++) t += w112[u * 128 + v * 8 + w] * f1[v * 3 + j];
                        s += wj * t;
                    }
                }
                val = C2_ * s;
            } else if (g >= 80) {
                const int u = (g - 80) / 5, i2 = (g - 80) % 5;
                if (i2 == k) {
                    float s = 0.f;
#pragma unroll
                    for (int v = 0; v < 32; v++) s += w202[u * 256 + v * 8 + w] * f0[v];
                    val = C2_ * INV_S5_ * s + wl2[u * 8 + w] * RS2_;
                }
            }
        }
    }
    const int kchunk = g >> 5;
    const int kstep  = (g >> 3) & 3;
    const int idx    = (g >> 2) & 1;
    const int lane   = (o & 7) * 4 + (g & 3);
    const int nf     = o >> 3;
    const int np     = nf >> 1;
    const int half   = nf & 1;
    // 16B granule holds {nf_even idx0, nf_even idx1, nf_odd idx0, nf_odd idx1}
    d_Bf[(((kchunk * 4 + kstep) * 8 + np) * 32 + lane) * 4 + half * 2 + idx] =
        __uint_as_float(f2tf32(val));
}

// ---------------------------------------------------------------------------
// tf32 GEMM: CTA 64 atoms x 128 outputs, BK=32 x 4 chunks, 128 threads.
// 4 warps: 2(M) x 2(N); warp tile 32x64 = 2 m-frags x 8 n-frags (m16n8k8).
// A: 2-stage cp.async, XOR-swizzled raw rows (8KB/stage).
// B: 2-stage cp.async from L2-resident d_Bf (16KB/stage), LDS.128 frag pairs.
// Block sparsity of M: kc=0 has zero cols >=80; kc=3 zero cols <32; cols
// 120..127 always zero -> skip those MMAs / B loads (exact zeros, bitwise
// identical result).
// ---------------------------------------------------------------------------
#define A_STAGE_F 2048                 // 64 rows * 32 floats = 8KB/stage
#define B_STAGE_F 4096                 // 16KB/stage

extern __shared__ float smem_dyn[];

__device__ __forceinline__ void cp_async16(uint32_t dst, const void* src, int sz) {
    asm volatile("cp.async.cg.shared.global [%0], [%1], 16, %2;"
                 :: "r"(dst), "l"(src), "r"(sz));
}

__global__ __launch_bounds__(128, 4) void coupling_gemm_tf32(
    const float* __restrict__ G, float* __restrict__ out, int n)
{
    float* Bs = smem_dyn;                      // [2][4096]
    float* As = smem_dyn + 2 * B_STAGE_F;      // [2][2048]
    const uint32_t as_base = (uint32_t)__cvta_generic_to_shared(As);
    const uint32_t bs_base = (uint32_t)__cvta_generic_to_shared(Bs);

    const int tid   = threadIdx.x;
    const int lane  = tid & 31;
    const int warp  = tid >> 5;
    const int warpM = warp >> 1;   // 0..1 -> rows warpM*32
    const int warpN = warp & 1;    // 0..1 -> cols warpN*64
    const long long z0 = (long long)blockIdx.x * 64;

    // A loader: chunk kc -> buf kc&1. 64 rows x 32 floats = 512 x 16B granules.
    auto issue_A = [&](int kc) {
#pragma unroll
        for (int i = 0; i < 4; i++) {
            const int seg = i * 128 + tid;     // 0..511
            const int row = seg >> 3;          // 0..63
            const int q   = seg & 7;           // 16B granule within row
            const int kb  = kc * 32 + q * 4;
            const long long gr = z0 + row;
            const bool ok = (gr < (long long)n) && (kb <= 116);
            const uint32_t dst = as_base + (kc & 1) * (A_STAGE_F * 4)
                               + row * 128 + ((q ^ (row & 7)) << 4);
            cp_async16(dst, G + gr * 120 + kb, ok ? 16 : 0);
        }
    };
    // B loader: chunk kc -> buf kc&1; skip known-zero block regions.
    auto issue_B = [&](int kc) {
#pragma unroll
        for (int i = 0; i < 8; i++) {
            const int seg = i * 128 + tid;     // 0..1023 (16B granules)
            const int np  = (seg >> 5) & 7;    // n-pair 0..7
            const bool ok = !((kc == 0 && np >= 5) || (kc == 3 && np < 2));
            const uint32_t dst = bs_base + (kc & 1) * (B_STAGE_F * 4) + seg * 16;
            cp_async16(dst, d_Bf + kc * B_STAGE_F + seg * 4, ok ? 16 : 0);
        }
    };

    issue_A(0); issue_B(0);
    asm volatile("cp.async.commit_group;");
    issue_A(1); issue_B(1);
    asm volatile("cp.async.commit_group;");

    float c[2][8][4];
#pragma unroll
    for (int mf = 0; mf < 2; mf++)
#pragma unroll
        for (int nf = 0; nf < 8; nf++)
#pragma unroll
            for (int q = 0; q < 4; q++) c[mf][nf][q] = 0.f;

#pragma unroll
    for (int kc = 0; kc < 4; kc++) {
        if (kc < 3) asm volatile("cp.async.wait_group 1;");
        else        asm volatile("cp.async.wait_group 0;");
        __syncthreads();

        // active local-nf window for this (kc, warpN):
        //  kc=0, warpN=1: only nf 0..1 (cols 64..79); kc=3, warpN=0: nf 4..7;
        //  warpN=1 always skips nf 7 (cols 120..127, padded zero).
        const int nf_lo = (kc == 3 && warpN == 0) ? 4 : 0;
        const int nf_hi = (warpN == 1) ? ((kc == 0) ? 2 : 7) : 8;

        const float* Ab = As + (kc & 1) * A_STAGE_F;
        const float* Bb = Bs + (kc & 1) * B_STAGE_F;
#pragma unroll
        for (int ks = 0; ks < 4; ks++) {
            // B frags: one LDS.128 per nf-pair
            uint32_t b[8][2];
#pragma unroll
            for (int npl = 0; npl < 4; npl++) {
                if (2 * npl + 1 >= nf_lo && 2 * npl < nf_hi) {
                    const int np = warpN * 4 + npl;
                    const float4 bv = *(const float4*)
                        &Bb[((ks * 8 + np) * 32 + lane) * 4];
                    b[npl * 2][0]     = __float_as_uint(bv.x);
                    b[npl * 2][1]     = __float_as_uint(bv.y);
                    b[npl * 2 + 1][0] = __float_as_uint(bv.z);
                    b[npl * 2 + 1][1] = __float_as_uint(bv.w);
                }
            }
            // A frags: raw f32 LDS (XOR-swizzled) + cvt to tf32
            uint32_t a[2][4];
#pragma unroll
            for (int mf = 0; mf < 2; mf++) {
                const int r0 = warpM * 32 + mf * 16 + (lane >> 2);
                const int r1 = r0 + 8;
                const int c0 = (lane & 3);
                const int q0 = ks * 2, q1 = ks * 2 + 1;
                a[mf][0] = f2tf32(Ab[r0 * 32 + ((q0 ^ (r0 & 7)) << 2) + c0]);
                a[mf][1] = f2tf32(Ab[r1 * 32 + ((q0 ^ (r1 & 7)) << 2) + c0]);
                a[mf][2] = f2tf32(Ab[r0 * 32 + ((q1 ^ (r0 & 7)) << 2) + c0]);
                a[mf][3] = f2tf32(Ab[r1 * 32 + ((q1 ^ (r1 & 7)) << 2) + c0]);
            }
#pragma unroll
            for (int mf = 0; mf < 2; mf++) {
#pragma unroll
                for (int nf = 0; nf < 8; nf++) {
                    if (nf >= nf_lo && nf < nf_hi) {
                        asm volatile(
                            "mma.sync.aligned.m16n8k8.row.col.f32.tf32.tf32.f32 "
                            "{%0,%1,%2,%3}, {%4,%5,%6,%7}, {%8,%9}, {%0,%1,%2,%3};"
                            : "+f"(c[mf][nf][0]), "+f"(c[mf][nf][1]),
                              "+f"(c[mf][nf][2]), "+f"(c[mf][nf][3])
                            : "r"(a[mf][0]), "r"(a[mf][1]), "r"(a[mf][2]), "r"(a[mf][3]),
                              "r"(b[nf][0]), "r"(b[nf][1]));
                    }
                }
            }
        }
        __syncthreads();
        if (kc < 2) {                  // refill buf (kc&1) with chunk kc+2
            issue_A(kc + 2); issue_B(kc + 2);
            asm volatile("cp.async.commit_group;");
        }
    }

    // ---- epilogue ----
#pragma unroll
    for (int mf = 0; mf < 2; mf++) {
        const int r0 = warpM * 32 + mf * 16 + (lane >> 2);
#pragma unroll
        for (int nf = 0; nf < 8; nf++) {
            const int col = warpN * 64 + nf * 8 + (lane & 3) * 2;
            if (col >= 120) continue;
            const long long row = z0 + r0;
            if (row < (long long)n)
                *(float2*)(out + row * 120 + col) =
                    make_float2(c[mf][nf][0], c[mf][nf][1]);
            if (row + 8 < (long long)n)
                *(float2*)(out + (row + 8) * 120 + col) =
                    make_float2(c[mf][nf][2], c[mf][nf][3]);
        }
    }
}

extern "C" void kernel_launch(void* const* d_in, const int* in_sizes, int n_in,
                              void* d_out, int out_size)
{
    const float* geom  = (const float*)d_in[0];
    const float* field = (const float*)d_in[1];
    const float* w000  = (const float*)d_in[2];
    const float* w011  = (const float*)d_in[3];
    const float* w101  = (const float*)d_in[4];
    const float* w110  = (const float*)d_in[5];
    const float* w112  = (const float*)d_in[6];
    const float* w202  = (const float*)d_in[7];
    const float* w211  = (const float*)d_in[8];
    const float* wl0   = (const float*)d_in[9];
    const float* wl1   = (const float*)d_in[10];
    const float* wl2   = (const float*)d_in[11];

    const int n = in_sizes[0] / 120;

    const int smem_bytes = (2 * B_STAGE_F + 2 * A_STAGE_F) * 4;   // 48KB
    cudaFuncSetAttribute(coupling_gemm_tf32,
                         cudaFuncAttributeMaxDynamicSharedMemorySize, smem_bytes);

    build_M<<<128, 128>>>(field, w000, w011, w101, w110, w112, w202, w211,
                          wl0, wl1, wl2);
    coupling_gemm_tf32<<<(n + 63) / 64, 128, smem_bytes>>>(geom, (float*)d_out, n);
}

// round 16
// speedup vs baseline: 1.0746x; 1.0746x over previous
#include <cuda_runtime.h>
#include <cstdint>

// Effective matrix, tf32, mma-fragment order, nf-pairwise 16B-packed:
// d_Bf[kchunk][kstep][npair][lane][half][idx], 4*4*8*32*2*2 = 16384 floats
__device__ float d_Bf[16384];

// ---- constants (match reference float32 values) ----
#define C0_     0.02795084971874737f   // sqrt(1/1280)
#define C1_     0.05103103630798288f   // sqrt(3/1152)
#define C2_     0.09882117688026186f   // sqrt(5/512)
#define INV_S3_ 0.57735026918962576f
#define INV_S5_ 0.44721359549995794f
#define RS0_    0.17677669529663687f   // 1/sqrt(32)
#define RS1_    0.25f                  // 1/sqrt(16)
#define RS2_    0.35355339059327373f   // 1/sqrt(8)

__device__ __forceinline__ void make_w3j(float C[3][3][5]) {
    const float s2 = 0.7071067811865476f;
    const float s6 = 0.4082482904638630f;
    const float i5 = 0.4472135954999579f;
#pragma unroll
    for (int i = 0; i < 3; i++)
#pragma unroll
        for (int j = 0; j < 3; j++)
#pragma unroll
            for (int k = 0; k < 5; k++) C[i][j][k] = 0.f;
    C[0][2][0] = s2;  C[2][0][0] = s2;
    C[0][1][1] = s2;  C[1][0][1] = s2;
    C[1][1][2] = 2.0f * s6;
    C[0][0][2] = -s6; C[2][2][2] = -s6;
    C[1][2][3] = s2;  C[2][1][3] = s2;
    C[2][2][4] = s2;  C[0][0][4] = -s2;
#pragma unroll
    for (int i = 0; i < 3; i++)
#pragma unroll
        for (int j = 0; j < 3; j++)
#pragma unroll
            for (int k = 0; k < 5; k++) C[i][j][k] *= i5;
}

__device__ __forceinline__ uint32_t f2tf32(float v) {
    uint32_t t;
    asm("cvt.rna.tf32.f32 %0, %1;" : "=r"(t) : "f"(v));
    return t;
}

// One thread per (o, g) entry of the effective 120x120 map (padded 128x128).
__global__ void build_M(const float* __restrict__ field,
                        const float* __restrict__ w000,
                        const float* __restrict__ w011,
                        const float* __restrict__ w101,
                        const float* __restrict__ w110,
                        const float* __restrict__ w112,
                        const float* __restrict__ w202,
                        const float* __restrict__ w211,
                        const float* __restrict__ wl0,
                        const float* __restrict__ wl1,
                        const float* __restrict__ wl2)
{
    const int o = blockIdx.x;
    const int g = threadIdx.x;
    const float* f0 = field;
    const float* f1 = field + 32;

    float val = 0.f;
    if (o < 120 && g < 120) {
        float W[3][3][5];
        make_w3j(W);
        if (o < 32) {
            const int w = o;
            if (g < 32) {
                const int u = g;
                float s = 0.f;
#pragma unroll
                for (int v = 0; v < 32; v++) s += w000[u * 1024 + v * 32 + w] * f0[v];
                val = C0_ * s + wl0[u * 32 + w] * RS0_;
            } else if (g < 80) {
                const int u = (g - 32) / 3, i = (g - 32) % 3;
                float s = 0.f;
#pragma unroll
                for (int v = 0; v < 16; v++) s += w110[u * 512 + v * 32 + w] * f1[v * 3 + i];
                val = C0_ * INV_S3_ * s;
            }
        } else if (o < 80) {
            const int w = (o - 32) / 3, j = (o - 32) % 3;
            if (g < 32) {
                const int u = g;
                float s = 0.f;
#pragma unroll
                for (int v = 0; v < 16; v++) s += w011[u * 256 + v * 16 + w] * f1[v * 3 + j];
                val = C1_ * INV_S3_ * s;
            } else if (g < 80) {
                const int u = (g - 32) / 3, i = (g - 32) % 3;
                if (i == j) {
                    float s = 0.f;
#pragma unroll
                    for (int v = 0; v < 32; v++) s += w101[u * 512 + v * 16 + w] * f0[v];
                    val = C1_ * INV_S3_ * s + wl1[u * 16 + w] * RS1_;
                }
            } else {
                const int u = (g - 80) / 5, k = (g - 80) % 5;
                float s = 0.f;
#pragma unroll
                for (int i = 0; i < 3; i++) {
                    const float wj = W[i][j][k];
                    if (wj != 0.f) {
                        float t = 0.f;
#pragma unroll
                        for (int v = 0; v < 16; v++) t += w211[u * 256 + v * 16 + w] * f1[v * 3 + i];
                        s += wj * t;
                    }
                }
                val = C1_ * s;
            }
        } else {
            const int w = (o - 80) / 5, k = (o - 80) % 5;
            if (g >= 32 && g < 80) {
                const int u = (g - 32) / 3, i = (g - 32) % 3;
                float s = 0.f;
#pragma unroll
                for (int j = 0; j < 3; j++) {
                    const float wj = W[i][j][k];
                    if (wj != 0.f) {
                        float t = 0.f;
#pragma unroll
                        for (int v = 0; v < 16; v++) t += w112[u * 128 + v * 8 + w] * f1[v * 3 + j];
                        s += wj * t;
                    }
                }
                val = C2_ * s;
            } else if (g >= 80) {
                const int u = (g - 80) / 5, i2 = (g - 80) % 5;
                if (i2 == k) {
                    float s = 0.f;
#pragma unroll
                    for (int v = 0; v < 32; v++) s += w202[u * 256 + v * 8 + w] * f0[v];
                    val = C2_ * INV_S5_ * s + wl2[u * 8 + w] * RS2_;
                }
            }
        }
    }
    const int kchunk = g >> 5;
    const int kstep  = (g >> 3) & 3;
    const int idx    = (g >> 2) & 1;
    const int lane   = (o & 7) * 4 + (g & 3);
    const int nf     = o >> 3;
    const int np     = nf >> 1;
    const int half   = nf & 1;
    // 16B granule holds {nf_even idx0, nf_even idx1, nf_odd idx0, nf_odd idx1}
    d_Bf[(((kchunk * 4 + kstep) * 8 + np) * 32 + lane) * 4 + half * 2 + idx] =
        __uint_as_float(f2tf32(val));
}

// ---------------------------------------------------------------------------
// tf32 GEMM: CTA 64 atoms x 128 outputs, BK=32 x 4 chunks, 128 threads.
// 4 warps: 2(M) x 2(N); warp tile 32x64 = 2 m-frags x 8 n-frags (m16n8k8).
// Block sparsity with COMPILE-TIME nf bounds (template dispatch per warpN/kc):
//  kc=0, warpN=1: nf 0..1;  kc=3, warpN=0: nf 4..7;  warpN=1: skip nf 7.
// ---------------------------------------------------------------------------
#define A_STAGE_F 2048                 // 64 rows * 32 floats = 8KB/stage
#define B_STAGE_F 4096                 // 16KB/stage

extern __shared__ float smem_dyn[];

__device__ __forceinline__ void cp_async16(uint32_t dst, const void* src, int sz) {
    asm volatile("cp.async.cg.shared.global [%0], [%1], 16, %2;"
                 :: "r"(dst), "l"(src), "r"(sz));
}

// One K-chunk of MMAs with compile-time nf window [NF_LO, NF_HI).
template<int NF_LO, int NF_HI>
__device__ __forceinline__ void do_chunk(const float* __restrict__ Ab,
                                         const float* __restrict__ Bb,
                                         int warpM, int warpN, int lane,
                                         float (&c)[2][8][4])
{
#pragma unroll
    for (int ks = 0; ks < 4; ks++) {
        // B frags: one LDS.128 per active nf-pair (bounds constexpr)
        uint32_t b[8][2];
#pragma unroll
        for (int npl = 0; npl < 4; npl++) {
            if (2 * npl + 1 >= NF_LO && 2 * npl < NF_HI) {
                const int np = warpN * 4 + npl;
                const float4 bv = *(const float4*)
                    &Bb[((ks * 8 + np) * 32 + lane) * 4];
                b[npl * 2][0]     = __float_as_uint(bv.x);
                b[npl * 2][1]     = __float_as_uint(bv.y);
                b[npl * 2 + 1][0] = __float_as_uint(bv.z);
                b[npl * 2 + 1][1] = __float_as_uint(bv.w);
            }
        }
        // A frags: raw f32 LDS (XOR-swizzled) + cvt to tf32
        uint32_t a[2][4];
#pragma unroll
        for (int mf = 0; mf < 2; mf++) {
            const int r0 = warpM * 32 + mf * 16 + (lane >> 2);
            const int r1 = r0 + 8;
            const int c0 = (lane & 3);
            const int q0 = ks * 2, q1 = ks * 2 + 1;
            a[mf][0] = f2tf32(Ab[r0 * 32 + ((q0 ^ (r0 & 7)) << 2) + c0]);
            a[mf][1] = f2tf32(Ab[r1 * 32 + ((q0 ^ (r1 & 7)) << 2) + c0]);
            a[mf][2] = f2tf32(Ab[r0 * 32 + ((q1 ^ (r0 & 7)) << 2) + c0]);
            a[mf][3] = f2tf32(Ab[r1 * 32 + ((q1 ^ (r1 & 7)) << 2) + c0]);
        }
#pragma unroll
        for (int mf = 0; mf < 2; mf++) {
#pragma unroll
            for (int nf = NF_LO; nf < NF_HI; nf++) {
                asm volatile(
                    "mma.sync.aligned.m16n8k8.row.col.f32.tf32.tf32.f32 "
                    "{%0,%1,%2,%3}, {%4,%5,%6,%7}, {%8,%9}, {%0,%1,%2,%3};"
                    : "+f"(c[mf][nf][0]), "+f"(c[mf][nf][1]),
                      "+f"(c[mf][nf][2]), "+f"(c[mf][nf][3])
                    : "r"(a[mf][0]), "r"(a[mf][1]), "r"(a[mf][2]), "r"(a[mf][3]),
                      "r"(b[nf][0]), "r"(b[nf][1]));
            }
        }
    }
}

__global__ __launch_bounds__(128, 4) void coupling_gemm_tf32(
    const float* __restrict__ G, float* __restrict__ out, int n)
{
    float* Bs = smem_dyn;                      // [2][4096]
    float* As = smem_dyn + 2 * B_STAGE_F;      // [2][2048]
    const uint32_t as_base = (uint32_t)__cvta_generic_to_shared(As);
    const uint32_t bs_base = (uint32_t)__cvta_generic_to_shared(Bs);

    const int tid   = threadIdx.x;
    const int lane  = tid & 31;
    const int warp  = tid >> 5;
    const int warpM = warp >> 1;   // 0..1 -> rows warpM*32
    const int warpN = warp & 1;    // 0..1 -> cols warpN*64
    const long long z0 = (long long)blockIdx.x * 64;

    auto issue_A = [&](int kc) {
#pragma unroll
        for (int i = 0; i < 4; i++) {
            const int seg = i * 128 + tid;     // 0..511
            const int row = seg >> 3;          // 0..63
            const int q   = seg & 7;           // 16B granule within row
            const int kb  = kc * 32 + q * 4;
            const long long gr = z0 + row;
            const bool ok = (gr < (long long)n) && (kb <= 116);
            const uint32_t dst = as_base + (kc & 1) * (A_STAGE_F * 4)
                               + row * 128 + ((q ^ (row & 7)) << 4);
            cp_async16(dst, G + gr * 120 + kb, ok ? 16 : 0);
        }
    };
    auto issue_B = [&](int kc) {
#pragma unroll
        for (int i = 0; i < 8; i++) {
            const int seg = i * 128 + tid;     // 0..1023 (16B granules)
            const int np  = (seg >> 5) & 7;    // n-pair 0..7
            const bool ok = !((kc == 0 && np >= 5) || (kc == 3 && np < 2));
            const uint32_t dst = bs_base + (kc & 1) * (B_STAGE_F * 4) + seg * 16;
            cp_async16(dst, d_Bf + kc * B_STAGE_F + seg * 4, ok ? 16 : 0);
        }
    };

    issue_A(0); issue_B(0);
    asm volatile("cp.async.commit_group;");
    issue_A(1); issue_B(1);
    asm volatile("cp.async.commit_group;");

    float c[2][8][4];
#pragma unroll
    for (int mf = 0; mf < 2; mf++)
#pragma unroll
        for (int nf = 0; nf < 8; nf++)
#pragma unroll
            for (int q = 0; q < 4; q++) c[mf][nf][q] = 0.f;

#pragma unroll
    for (int kc = 0; kc < 4; kc++) {
        if (kc < 3) asm volatile("cp.async.wait_group 1;");
        else        asm volatile("cp.async.wait_group 0;");
        __syncthreads();

        const float* Ab = As + (kc & 1) * A_STAGE_F;
        const float* Bb = Bs + (kc & 1) * B_STAGE_F;

        // compile-time nf windows, dispatched once per chunk
        if (kc == 0) {
            if (warpN == 0) do_chunk<0, 8>(Ab, Bb, warpM, warpN, lane, c);
            else            do_chunk<0, 2>(Ab, Bb, warpM, warpN, lane, c);
        } else if (kc == 3) {
            if (warpN == 0) do_chunk<4, 8>(Ab, Bb, warpM, warpN, lane, c);
            else            do_chunk<0, 7>(Ab, Bb, warpM, warpN, lane, c);
        } else {
            if (warpN == 0) do_chunk<0, 8>(Ab, Bb, warpM, warpN, lane, c);
            else            do_chunk<0, 7>(Ab, Bb, warpM, warpN, lane, c);
        }

        __syncthreads();
        if (kc < 2) {                  // refill buf (kc&1) with chunk kc+2
            issue_A(kc + 2); issue_B(kc + 2);
            asm volatile("cp.async.commit_group;");
        }
    }

    // ---- epilogue ----
#pragma unroll
    for (int mf = 0; mf < 2; mf++) {
        const int r0 = warpM * 32 + mf * 16 + (lane >> 2);
#pragma unroll
        for (int nf = 0; nf < 8; nf++) {
            const int col = warpN * 64 + nf * 8 + (lane & 3) * 2;
            if (col >= 120) continue;
            const long long row = z0 + r0;
            if (row < (long long)n)
                *(float2*)(out + row * 120 + col) =
                    make_float2(c[mf][nf][0], c[mf][nf][1]);
            if (row + 8 < (long long)n)
                *(float2*)(out + (row + 8) * 120 + col) =
                    make_float2(c[mf][nf][2], c[mf][nf][3]);
        }
    }
}

extern "C" void kernel_launch(void* const* d_in, const int* in_sizes, int n_in,
                              void* d_out, int out_size)
{
    const float* geom  = (const float*)d_in[0];
    const float* field = (const float*)d_in[1];
    const float* w000  = (const float*)d_in[2];
    const float* w011  = (const float*)d_in[3];
    const float* w101  = (const float*)d_in[4];
    const float* w110  = (const float*)d_in[5];
    const float* w112  = (const float*)d_in[6];
    const float* w202  = (const float*)d_in[7];
    const float* w211  = (const float*)d_in[8];
    const float* wl0   = (const float*)d_in[9];
    const float* wl1   = (const float*)d_in[10];
    const float* wl2   = (const float*)d_in[11];

    const int n = in_sizes[0] / 120;

    const int smem_bytes = (2 * B_STAGE_F + 2 * A_STAGE_F) * 4;   // 48KB
    cudaFuncSetAttribute(coupling_gemm_tf32,
                         cudaFuncAttributeMaxDynamicSharedMemorySize, smem_bytes);

    build_M<<<128, 128>>>(field, w000, w011, w101, w110, w112, w202, w211,
                          wl0, wl1, wl2);
    coupling_gemm_tf32<<<(n + 63) / 64, 128, smem_bytes>>>(geom, (float*)d_out, n);
}